// round 12
// baseline (speedup 1.0000x reference)
#include <cuda_runtime.h>

#define BB 64      // batch
#define SS 512     // sequence length
#define EE 256     // embedding dim
#define HH 512     // hidden
#define GG 2048    // 4*H gate rows

typedef unsigned long long u64;
typedef unsigned int u32;

// ---------------------------------------------------------------------------
// Device globals
// ---------------------------------------------------------------------------
__device__ u32 g_wf[128];                     // per-CTA h write-flags (monotonic)
__device__ u32 g_xgf[SS][32];                 // per-s xg ready flags (padded lines)
__device__ float g_xg[SS * GG * BB];          // x_gates [s][g][b]
__device__ float g_h[4][HH * BB];             // h ring: slot s&3 = h(s), [k][b]

// ---------------------------------------------------------------------------
// f32x2 helpers (packed FFMA2/FADD2 -- only reachable via PTX)
// ---------------------------------------------------------------------------
__device__ __forceinline__ u64 fma2(u64 a, u64 b, u64 c) {
    u64 d; asm("fma.rn.f32x2 %0, %1, %2, %3;" : "=l"(d) : "l"(a), "l"(b), "l"(c)); return d;
}
__device__ __forceinline__ u64 add2(u64 a, u64 b) {
    u64 d; asm("add.rn.f32x2 %0, %1, %2;" : "=l"(d) : "l"(a), "l"(b)); return d;
}
__device__ __forceinline__ u64 pack2(float x, float y) {
    u64 d; asm("mov.b64 %0, {%1, %2};" : "=l"(d) : "f"(x), "f"(y)); return d;
}
__device__ __forceinline__ float2 unpack2(u64 v) {
    float2 r; asm("mov.b64 {%0, %1}, %2;" : "=f"(r.x), "=f"(r.y) : "l"(v)); return r;
}
__device__ __forceinline__ float sigf(float x) { return 1.f / (1.f + __expf(-x)); }
__device__ __forceinline__ float tanh_f(float x) { return 2.f / (1.f + __expf(-2.f * x)) - 1.f; }

// ---------------------------------------------------------------------------
// Phase A producer: 64-thread CTAs (gap fillers that co-schedule next to the
// persistent lstm CTAs). Tile 64 b x 32 g, K=256, BK=16; thread = 8M x 4N
// f32x2 (4 b-pairs x 4 g). Grid (64 g-blocks, 512 s), s-major launch order.
// After the tile store, release-bump g_xgf[s] (+64 per s per run).
// ---------------------------------------------------------------------------
__global__ void __launch_bounds__(64) xgates_gemm(
    const void* __restrict__ seq,
    const float* __restrict__ emb,
    const float* __restrict__ Wih,
    const float* __restrict__ bih,
    const float* __restrict__ bhh)
{
    __shared__ float  As[16][66];    // [k][b]
    __shared__ float2 Bs2[16][33];   // [k][g_local] duplicated {w,w}
    __shared__ int rows[64];
    __shared__ int s_is64;

    const int tid = threadIdx.x;
    const int s   = blockIdx.y;
    const int g0  = blockIdx.x * 32;

    if (tid == 0) s_is64 = 1;
    __syncthreads();
    if (((const u32*)seq)[2 * tid + 1] != 0u) s_is64 = 0;
    __syncthreads();
    {
        int idx;
        if (s_is64) idx = (int)((const long long*)seq)[tid * SS + s];
        else        idx = ((const int*)seq)[tid * SS + s];
        rows[tid] = idx;
    }
    __syncthreads();

    const int tx = tid & 7;           // M dir: 4 b-pairs
    const int ty = tid >> 3;          // N dir: 4 g each
    const int wrow = tid >> 1;        // W loader: g row
    const int wk   = (tid & 1) * 8;   // k offset (8 floats)

    const float* aptr = emb + (size_t)rows[tid] * EE;          // 16 floats/tile
    const float* wptr = Wih + (size_t)(g0 + wrow) * EE + wk;   // 8 floats/tile

    u64 cc[4][4];
    #pragma unroll
    for (int p = 0; p < 4; p++)
        #pragma unroll
        for (int jn = 0; jn < 4; jn++) cc[p][jn] = 0ull;

    // prefetch tile 0
    float4 ra[4], rw0, rw1;
    #pragma unroll
    for (int i = 0; i < 4; i++) ra[i] = *(const float4*)(aptr + i * 4);
    rw0 = *(const float4*)wptr;
    rw1 = *(const float4*)(wptr + 4);

    for (int k0 = 0; k0 < EE; k0 += 16) {
        #pragma unroll
        for (int i = 0; i < 4; i++) {
            As[i * 4 + 0][tid] = ra[i].x; As[i * 4 + 1][tid] = ra[i].y;
            As[i * 4 + 2][tid] = ra[i].z; As[i * 4 + 3][tid] = ra[i].w;
        }
        Bs2[wk + 0][wrow] = make_float2(rw0.x, rw0.x);
        Bs2[wk + 1][wrow] = make_float2(rw0.y, rw0.y);
        Bs2[wk + 2][wrow] = make_float2(rw0.z, rw0.z);
        Bs2[wk + 3][wrow] = make_float2(rw0.w, rw0.w);
        Bs2[wk + 4][wrow] = make_float2(rw1.x, rw1.x);
        Bs2[wk + 5][wrow] = make_float2(rw1.y, rw1.y);
        Bs2[wk + 6][wrow] = make_float2(rw1.z, rw1.z);
        Bs2[wk + 7][wrow] = make_float2(rw1.w, rw1.w);
        __syncthreads();

        if (k0 + 16 < EE) {   // next tile's loads overlap compute
            #pragma unroll
            for (int i = 0; i < 4; i++)
                ra[i] = *(const float4*)(aptr + k0 + 16 + i * 4);
            rw0 = *(const float4*)(wptr + k0 + 16);
            rw1 = *(const float4*)(wptr + k0 + 20);
        }

        #pragma unroll
        for (int kk = 0; kk < 16; kk++) {
            u64 a0p = *(const u64*)&As[kk][tx * 2 + 0];
            u64 a1p = *(const u64*)&As[kk][tx * 2 + 16];
            u64 a2p = *(const u64*)&As[kk][tx * 2 + 32];
            u64 a3p = *(const u64*)&As[kk][tx * 2 + 48];
            u64 w0 = *(const u64*)&Bs2[kk][ty * 4 + 0];
            u64 w1 = *(const u64*)&Bs2[kk][ty * 4 + 1];
            u64 w2 = *(const u64*)&Bs2[kk][ty * 4 + 2];
            u64 w3 = *(const u64*)&Bs2[kk][ty * 4 + 3];
            cc[0][0] = fma2(a0p, w0, cc[0][0]); cc[1][0] = fma2(a1p, w0, cc[1][0]);
            cc[2][0] = fma2(a2p, w0, cc[2][0]); cc[3][0] = fma2(a3p, w0, cc[3][0]);
            cc[0][1] = fma2(a0p, w1, cc[0][1]); cc[1][1] = fma2(a1p, w1, cc[1][1]);
            cc[2][1] = fma2(a2p, w1, cc[2][1]); cc[3][1] = fma2(a3p, w1, cc[3][1]);
            cc[0][2] = fma2(a0p, w2, cc[0][2]); cc[1][2] = fma2(a1p, w2, cc[1][2]);
            cc[2][2] = fma2(a2p, w2, cc[2][2]); cc[3][2] = fma2(a3p, w2, cc[3][2]);
            cc[0][3] = fma2(a0p, w3, cc[0][3]); cc[1][3] = fma2(a1p, w3, cc[1][3]);
            cc[2][3] = fma2(a2p, w3, cc[2][3]); cc[3][3] = fma2(a3p, w3, cc[3][3]);
        }
        __syncthreads();
    }

    // store xg[s][g][b], b-pairs at b = p*16 + tx*2
    #pragma unroll
    for (int jn = 0; jn < 4; jn++) {
        int g = g0 + ty * 4 + jn;
        float bsum = bih[g] + bhh[g];
        #pragma unroll
        for (int p = 0; p < 4; p++) {
            float2 v = unpack2(cc[p][jn]);
            *(float2*)&g_xg[(size_t)s * (GG * BB) + (size_t)g * BB + p * 16 + tx * 2] =
                make_float2(v.x + bsum, v.y + bsum);
        }
    }
    __syncthreads();
    if (tid == 0) {
        asm volatile("red.release.gpu.global.add.u32 [%0], %1;"
                     :: "l"(&g_xgf[s][0]), "r"(1u) : "memory");
    }
}

// ---------------------------------------------------------------------------
// Phase B: persistent LSTM recurrence (R10 structure), runs CONCURRENTLY
// with xgates_gemm. Adds one xg-flag acquire-poll per warp per step
// (target = run*64 + 64, run derived from this CTA's monotonic g_wf).
// ---------------------------------------------------------------------------
__global__ void __launch_bounds__(256, 1) lstm_kernel(
    const float* __restrict__ Whh, float* __restrict__ out, int write_c)
{
    extern __shared__ float smf[];
    float*  Ws  = smf;                      // (st*512+k)*2 : {w_jA, w_jB}
    float2* scp = (float2*)(smf + 8192);    // [st8][kr8][b64] float2
    __shared__ u32 s_base;

    const int tid  = threadIdx.x;
    const int wi   = tid >> 5;
    const int lane = tid & 31;
    const int cta  = blockIdx.x;
    const int j0   = cta * 4;
    const int kbase = wi * 64;

    if (tid == 0) s_base = g_wf[cta];

    #pragma unroll
    for (int st = 0; st < 8; st++) {
        int g = st >> 1, jp = st & 1;
        const float* r0 = Whh + (size_t)(g * HH + j0 + 2 * jp) * HH;
        const float* r1 = r0 + HH;
        #pragma unroll
        for (int i = 0; i < 2; i++) {
            int k = tid + i * 256;
            *(float2*)&Ws[(st * 512 + k) * 2] = make_float2(r0[k], r1[k]);
        }
    }
    __syncthreads();

    const int b  = tid & 63;
    const int jj = tid >> 6;
    const int j  = j0 + jj;
    const int jp_r = jj >> 1;
    const int comp = jj & 1;
    const u32 base = s_base;                  // = run * 512
    const u32 xtarget0 = (base / 512u) * 64u + 64u;

    float c_reg = 0.f, h_val = 0.f;

    #pragma unroll 1
    for (int s = 0; s < SS; s++) {
        // ---- wait for xg(s) from the concurrent producer ----
        {
            int ok, first = 1;
            do {
                if (!first) __nanosleep(32);
                first = 0;
                ok = 1;
                if (lane == 0) {
                    u32 f;
                    asm volatile("ld.acquire.gpu.global.u32 %0, [%1];"
                                 : "=r"(f) : "l"(&g_xgf[s][0]));
                    ok = ((int)(f - xtarget0) >= 0);
                }
            } while (__all_sync(0xffffffffu, ok) == 0);
        }
        float xgv[4];
        const float* xgs = g_xg + (size_t)s * (GG * BB);
        #pragma unroll
        for (int g = 0; g < 4; g++)
            xgv[g] = __ldg(&xgs[(g * HH + j) * BB + b]);

        u64 acc[8][2];
        #pragma unroll
        for (int st = 0; st < 8; st++) { acc[st][0] = 0ull; acc[st][1] = 0ull; }

        if (s > 0) {
            // single wait: the 16 producer CTAs of OUR k-range
            const u32 target = base + (u32)s;
            int ok, first = 1;
            do {
                if (!first) __nanosleep(20);
                first = 0;
                ok = 1;
                if (lane < 16) {
                    u32 f;
                    asm volatile("ld.acquire.gpu.global.u32 %0, [%1];"
                                 : "=r"(f) : "l"(&g_wf[wi * 16 + lane]));
                    ok = ((int)(f - target) >= 0);
                }
            } while (__all_sync(0xffffffffu, ok) == 0);

            const float2* hsrc = (const float2*)g_h[(s - 1) & 3];  // [k][b/2]
            float2 hreg[4][8];
            #pragma unroll
            for (int c = 0; c < 3; c++)
                #pragma unroll
                for (int i = 0; i < 8; i++)
                    hreg[c][i] = __ldcg(&hsrc[(kbase + c * 8 + i) * 32 + lane]);

            #pragma unroll
            for (int c = 0; c < 8; c++) {
                const int cur = c & 3;
                if (c < 5) {
                    const int pb = (c + 3) & 3;
                    const int kn = kbase + (c + 3) * 8;
                    #pragma unroll
                    for (int i = 0; i < 8; i++)
                        hreg[pb][i] = __ldcg(&hsrc[(kn + i) * 32 + lane]);
                }
                const int kg0 = kbase + c * 8;
                #pragma unroll
                for (int kk = 0; kk < 8; kk += 2) {
                    const int kg = kg0 + kk;
                    float2 v0 = hreg[cur][kk];
                    float2 v1 = hreg[cur][kk + 1];
                    u64 dA0 = pack2(v0.x, v0.x);
                    u64 dB0 = pack2(v0.y, v0.y);
                    u64 dA1 = pack2(v1.x, v1.x);
                    u64 dB1 = pack2(v1.y, v1.y);
                    #pragma unroll
                    for (int st = 0; st < 8; st++) {
                        ulonglong2 wv = *(const ulonglong2*)&Ws[(st * 512 + kg) * 2];
                        acc[st][0] = fma2(dA0, wv.x, acc[st][0]);
                        acc[st][1] = fma2(dB0, wv.x, acc[st][1]);
                        acc[st][0] = fma2(dA1, wv.y, acc[st][0]);
                        acc[st][1] = fma2(dB1, wv.y, acc[st][1]);
                    }
                }
            }
        }

        // partials -> scratch [st][kr][b], one STS.128 per stream
        #pragma unroll
        for (int st = 0; st < 8; st++) {
            float2 p0 = *(float2*)&acc[st][0];
            float2 p1 = *(float2*)&acc[st][1];
            *(float4*)&scp[(st * 8 + wi) * 64 + 2 * lane] =
                make_float4(p0.x, p0.y, p1.x, p1.y);
        }
        __syncthreads();

        // cross-warp reduce (packed f32x2) + gates
        float gt[4];
        #pragma unroll
        for (int g = 0; g < 4; g++) {
            int st = g * 2 + jp_r;
            const u64* rb = (const u64*)&scp[(st * 8) * 64 + b];
            u64 v0 = add2(rb[0 * 64], rb[1 * 64]);
            u64 v1 = add2(rb[2 * 64], rb[3 * 64]);
            u64 v2 = add2(rb[4 * 64], rb[5 * 64]);
            u64 v3 = add2(rb[6 * 64], rb[7 * 64]);
            float2 r = unpack2(add2(add2(v0, v1), add2(v2, v3)));
            gt[g] = (comp ? r.y : r.x) + xgv[g];
        }
        float ig = sigf(gt[0]), fg = sigf(gt[1]);
        float gg = tanh_f(gt[2]), og = sigf(gt[3]);
        c_reg = fg * c_reg + ig * gg;
        h_val = og * tanh_f(c_reg);

        __stcg(&g_h[s & 3][j * 64 + b], h_val);
        __syncthreads();
        if (tid == 0) {
            asm volatile("red.release.gpu.global.add.u32 [%0], %1;"
                         :: "l"(&g_wf[cta]), "r"(1u) : "memory");
        }
    }

    out[b * HH + j] = h_val;
    if (write_c) out[BB * HH + b * HH + j] = c_reg;
}

// ---------------------------------------------------------------------------
// kernel_launch: fork producer onto a second stream so gemm and lstm run
// CONCURRENTLY under graph capture (fork/join with disable-timing events).
// Stream/events created once, outside capture (first correctness call).
// ---------------------------------------------------------------------------
extern "C" void kernel_launch(void* const* d_in, const int* in_sizes, int n_in,
                              void* d_out, int out_size)
{
    const void*  seq = d_in[0];
    const float* emb = (const float*)d_in[1];
    const float* Wih = (const float*)d_in[2];
    const float* Whh = (const float*)d_in[3];
    const float* bih = (const float*)d_in[4];
    const float* bhh = (const float*)d_in[5];
    float* out = (float*)d_out;

    (void)in_sizes; (void)n_in;
    int write_c = (out_size >= 2 * BB * HH) ? 1 : 0;

    static cudaStream_t s2 = nullptr;
    static cudaEvent_t eFork = nullptr, eJoin = nullptr;
    if (!s2) {
        cudaStreamCreateWithFlags(&s2, cudaStreamNonBlocking);
        cudaEventCreateWithFlags(&eFork, cudaEventDisableTiming);
        cudaEventCreateWithFlags(&eJoin, cudaEventDisableTiming);
    }

    static const int kSmem = (8192 + 8192) * (int)sizeof(float);
    cudaFuncSetAttribute(lstm_kernel, cudaFuncAttributeMaxDynamicSharedMemorySize, kSmem);

    cudaEventRecord(eFork, 0);
    cudaStreamWaitEvent(s2, eFork, 0);
    xgates_gemm<<<dim3(GG / 32, SS), 64, 0, s2>>>(seq, emb, Wih, bih, bhh);
    lstm_kernel<<<HH / 4, 256, kSmem>>>(Whh, out, write_c);
    cudaEventRecord(eJoin, s2);
    cudaStreamWaitEvent(0, eJoin, 0);
}

// round 13
// speedup vs baseline: 1.0878x; 1.0878x over previous
#include <cuda_runtime.h>

#define BB 64      // batch
#define SS 512     // sequence length
#define EE 256     // embedding dim
#define HH 512     // hidden
#define GG 2048    // 4*H gate rows

typedef unsigned long long u64;
typedef unsigned int u32;

// ---------------------------------------------------------------------------
// Device globals
// ---------------------------------------------------------------------------
__device__ u32 g_wf[128];                     // per-CTA h write-flags (monotonic)
__device__ float g_xg[SS * GG * BB];          // x_gates [s][g][b]
__device__ float g_h[4][HH * BB];             // h ring: slot s&3 = h(s), [k][b]

// ---------------------------------------------------------------------------
// f32x2 helpers (packed FFMA2/FADD2 -- only reachable via PTX)
// ---------------------------------------------------------------------------
__device__ __forceinline__ u64 fma2(u64 a, u64 b, u64 c) {
    u64 d; asm("fma.rn.f32x2 %0, %1, %2, %3;" : "=l"(d) : "l"(a), "l"(b), "l"(c)); return d;
}
__device__ __forceinline__ u64 add2(u64 a, u64 b) {
    u64 d; asm("add.rn.f32x2 %0, %1, %2;" : "=l"(d) : "l"(a), "l"(b)); return d;
}
__device__ __forceinline__ u64 pack2(float x, float y) {
    u64 d; asm("mov.b64 %0, {%1, %2};" : "=l"(d) : "f"(x), "f"(y)); return d;
}
__device__ __forceinline__ float2 unpack2(u64 v) {
    float2 r; asm("mov.b64 {%0, %1}, %2;" : "=f"(r.x), "=f"(r.y) : "l"(v)); return r;
}
__device__ __forceinline__ float sigf(float x) { return 1.f / (1.f + __expf(-x)); }
__device__ __forceinline__ float tanh_f(float x) { return 2.f / (1.f + __expf(-2.f * x)) - 1.f; }

// ---------------------------------------------------------------------------
// Phase A: x_gates[s][g][b] = emb[seq[b][s]] . W_ih[g] + b_ih[g] + b_hh[g]
// (R10 version, measured ~928us: 128x64 tile, BK=16, 8Mx4N f32x2, reg-staged
// double buffering, plain stores)
// ---------------------------------------------------------------------------
__global__ void __launch_bounds__(256) xgates_gemm(
    const void* __restrict__ seq,
    const float* __restrict__ emb,
    const float* __restrict__ Wih,
    const float* __restrict__ bih,
    const float* __restrict__ bhh)
{
    __shared__ float  As[16][132];
    __shared__ float2 Bs2[16][66];
    __shared__ int rows[128];
    __shared__ int s_is64;

    const int tid = threadIdx.x;
    const int s0 = blockIdx.y * 2;
    const int g0 = blockIdx.x * 64;

    if (tid == 0) s_is64 = 1;
    __syncthreads();
    if (tid < 64) {
        if (((const u32*)seq)[2 * tid + 1] != 0u) s_is64 = 0;
    }
    __syncthreads();
    if (tid < 128) {
        int b = tid & 63, sl = tid >> 6;
        int idx;
        if (s_is64) idx = (int)((const long long*)seq)[b * SS + s0 + sl];
        else        idx = ((const int*)seq)[b * SS + s0 + sl];
        rows[tid] = idx;
    }
    __syncthreads();

    const int tx = tid & 15;
    const int ty = tid >> 4;
    const int arow = tid >> 1;
    const int ak   = (tid & 1) * 8;
    const int wrow = tid >> 2;
    const int wk   = (tid & 3) * 4;

    const float* aptr = emb + (size_t)rows[arow] * EE + ak;
    const float* wptr = Wih + (size_t)(g0 + wrow) * EE + wk;

    u64 cc[4][4];
    #pragma unroll
    for (int p = 0; p < 4; p++)
        #pragma unroll
        for (int jn = 0; jn < 4; jn++) cc[p][jn] = 0ull;

    float4 ra0 = *(const float4*)aptr;
    float4 ra1 = *(const float4*)(aptr + 4);
    float4 rw  = *(const float4*)wptr;

    for (int k0 = 0; k0 < EE; k0 += 16) {
        As[ak + 0][arow] = ra0.x; As[ak + 1][arow] = ra0.y;
        As[ak + 2][arow] = ra0.z; As[ak + 3][arow] = ra0.w;
        As[ak + 4][arow] = ra1.x; As[ak + 5][arow] = ra1.y;
        As[ak + 6][arow] = ra1.z; As[ak + 7][arow] = ra1.w;
        Bs2[wk + 0][wrow] = make_float2(rw.x, rw.x);
        Bs2[wk + 1][wrow] = make_float2(rw.y, rw.y);
        Bs2[wk + 2][wrow] = make_float2(rw.z, rw.z);
        Bs2[wk + 3][wrow] = make_float2(rw.w, rw.w);
        __syncthreads();

        if (k0 + 16 < EE) {   // next tile's loads overlap compute
            ra0 = *(const float4*)(aptr + k0 + 16);
            ra1 = *(const float4*)(aptr + k0 + 20);
            rw  = *(const float4*)(wptr + k0 + 16);
        }

        #pragma unroll
        for (int kk = 0; kk < 16; kk++) {
            u64 a0p = *(const u64*)&As[kk][0 * 32 + tx * 2];
            u64 a1p = *(const u64*)&As[kk][1 * 32 + tx * 2];
            u64 a2p = *(const u64*)&As[kk][2 * 32 + tx * 2];
            u64 a3p = *(const u64*)&As[kk][3 * 32 + tx * 2];
            u64 w0 = *(const u64*)&Bs2[kk][ty * 4 + 0];
            u64 w1 = *(const u64*)&Bs2[kk][ty * 4 + 1];
            u64 w2 = *(const u64*)&Bs2[kk][ty * 4 + 2];
            u64 w3 = *(const u64*)&Bs2[kk][ty * 4 + 3];
            cc[0][0] = fma2(a0p, w0, cc[0][0]); cc[1][0] = fma2(a1p, w0, cc[1][0]);
            cc[2][0] = fma2(a2p, w0, cc[2][0]); cc[3][0] = fma2(a3p, w0, cc[3][0]);
            cc[0][1] = fma2(a0p, w1, cc[0][1]); cc[1][1] = fma2(a1p, w1, cc[1][1]);
            cc[2][1] = fma2(a2p, w1, cc[2][1]); cc[3][1] = fma2(a3p, w1, cc[3][1]);
            cc[0][2] = fma2(a0p, w2, cc[0][2]); cc[1][2] = fma2(a1p, w2, cc[1][2]);
            cc[2][2] = fma2(a2p, w2, cc[2][2]); cc[3][2] = fma2(a3p, w2, cc[3][2]);
            cc[0][3] = fma2(a0p, w3, cc[0][3]); cc[1][3] = fma2(a1p, w3, cc[1][3]);
            cc[2][3] = fma2(a2p, w3, cc[2][3]); cc[3][3] = fma2(a3p, w3, cc[3][3]);
        }
        __syncthreads();
    }

    #pragma unroll
    for (int jn = 0; jn < 4; jn++) {
        int g = g0 + ty * 4 + jn;
        float bsum = bih[g] + bhh[g];
        #pragma unroll
        for (int p = 0; p < 4; p++) {
            float2 v = unpack2(cc[p][jn]);
            int s = s0 + (p >> 1);
            int b = (p & 1) * 32 + tx * 2;
            *(float2*)&g_xg[(size_t)s * (GG * BB) + (size_t)g * BB + b] =
                make_float2(v.x + bsum, v.y + bsum);
        }
    }
}

// ---------------------------------------------------------------------------
// Phase B: persistent LSTM recurrence, dataflow-synced, 16 WARPS per CTA.
// 128 CTAs x 512 threads. CTA owns 4 h-columns (8 f32x2 streams, vector =
// j-pair). Warp wi owns k-range [wi*32,+32); lane owns b-pair (LDG.64).
// 4 warps/SMSP: scoreboard stalls (flag RT, h-load RT) of one warp are
// covered by the other three; per-SMSP FFMA2 budget unchanged (4096 cyc).
// One acquire-poll per warp per step over its 8 producer flags.
// SMEM: W pairs 32KB | scratch 64KB = 96KB.
// ---------------------------------------------------------------------------
__global__ void __launch_bounds__(512, 1) lstm_kernel(
    const float* __restrict__ Whh, float* __restrict__ out, int write_c)
{
    extern __shared__ float smf[];
    float*  Ws  = smf;                      // (st*512+k)*2 : {w_jA, w_jB}
    float2* scp = (float2*)(smf + 8192);    // [st8][kr16][b64] float2
    __shared__ u32 s_base;

    const int tid  = threadIdx.x;
    const int wi   = tid >> 5;              // warp = k-range index (0..15)
    const int lane = tid & 31;
    const int cta  = blockIdx.x;
    const int j0   = cta * 4;
    const int kbase = wi * 32;

    if (tid == 0) s_base = g_wf[cta];

    // W pairs: st = g*2+jp covers rows (g*H + j0+2jp, +1); 512 thr -> 1 f2/st
    #pragma unroll
    for (int st = 0; st < 8; st++) {
        int g = st >> 1, jp = st & 1;
        const float* r0 = Whh + (size_t)(g * HH + j0 + 2 * jp) * HH;
        const float* r1 = r0 + HH;
        *(float2*)&Ws[(st * 512 + tid) * 2] = make_float2(r0[tid], r1[tid]);
    }
    __syncthreads();

    const int b  = tid & 63;        // epilogue (tid < 256): one (b, j)
    const int jj = tid >> 6;        // 0..7; only 0..3 do epilogue
    const int j  = j0 + (jj & 3);
    const int jp_r = (jj & 3) >> 1;
    const int comp = jj & 1;
    const u32 base = s_base;

    float c_reg = 0.f, h_val = 0.f;

    #pragma unroll 1
    for (int s = 0; s < SS; s++) {
        // xg precomputed: L2-resident from GEMM
        float xgv[4];
        if (tid < 256) {
            const float* xgs = g_xg + (size_t)s * (GG * BB);
            #pragma unroll
            for (int g = 0; g < 4; g++)
                xgv[g] = __ldg(&xgs[(g * HH + j) * BB + b]);
        }

        u64 acc[8][2];
        #pragma unroll
        for (int st = 0; st < 8; st++) { acc[st][0] = 0ull; acc[st][1] = 0ull; }

        if (s > 0) {
            // single wait: the 8 producer CTAs of OUR 32-k range
            const u32 target = base + (u32)s;
            int ok, first = 1;
            do {
                if (!first) __nanosleep(20);
                first = 0;
                ok = 1;
                if (lane < 8) {
                    u32 f;
                    asm volatile("ld.acquire.gpu.global.u32 %0, [%1];"
                                 : "=r"(f) : "l"(&g_wf[wi * 8 + lane]));
                    ok = ((int)(f - target) >= 0);
                }
            } while (__all_sync(0xffffffffu, ok) == 0);

            const float2* hsrc = (const float2*)g_h[(s - 1) & 3];  // [k][b/2]
            float2 hreg[4][8];   // 4 chunks of 8 k; prefetch distance 3

            #pragma unroll
            for (int c = 0; c < 3; c++)
                #pragma unroll
                for (int i = 0; i < 8; i++)
                    hreg[c][i] = __ldcg(&hsrc[(kbase + c * 8 + i) * 32 + lane]);

            #pragma unroll
            for (int c = 0; c < 4; c++) {
                const int cur = c & 3;
                if (c < 1) {
                    const int pb = (c + 3) & 3;
                    const int kn = kbase + (c + 3) * 8;
                    #pragma unroll
                    for (int i = 0; i < 8; i++)
                        hreg[pb][i] = __ldcg(&hsrc[(kn + i) * 32 + lane]);
                }
                const int kg0 = kbase + c * 8;
                #pragma unroll
                for (int kk = 0; kk < 8; kk += 2) {
                    const int kg = kg0 + kk;
                    float2 v0 = hreg[cur][kk];
                    float2 v1 = hreg[cur][kk + 1];
                    u64 dA0 = pack2(v0.x, v0.x);   // b = 2*lane,   k = kg
                    u64 dB0 = pack2(v0.y, v0.y);   // b = 2*lane+1, k = kg
                    u64 dA1 = pack2(v1.x, v1.x);
                    u64 dB1 = pack2(v1.y, v1.y);
                    #pragma unroll
                    for (int st = 0; st < 8; st++) {
                        ulonglong2 wv = *(const ulonglong2*)&Ws[(st * 512 + kg) * 2];
                        acc[st][0] = fma2(dA0, wv.x, acc[st][0]);
                        acc[st][1] = fma2(dB0, wv.x, acc[st][1]);
                        acc[st][0] = fma2(dA1, wv.y, acc[st][0]);
                        acc[st][1] = fma2(dB1, wv.y, acc[st][1]);
                    }
                }
            }
        }

        // partials -> scratch [st][kr][b], one STS.128 per stream
        #pragma unroll
        for (int st = 0; st < 8; st++) {
            float2 p0 = *(float2*)&acc[st][0];
            float2 p1 = *(float2*)&acc[st][1];
            *(float4*)&scp[(st * 16 + wi) * 64 + 2 * lane] =
                make_float4(p0.x, p0.y, p1.x, p1.y);
        }
        __syncthreads();

        // cross-warp reduce (16 k-range partials, packed f32x2) + gates
        if (tid < 256) {
            float gt[4];
            #pragma unroll
            for (int g = 0; g < 4; g++) {
                int st = g * 2 + jp_r;
                const u64* rb = (const u64*)&scp[(st * 16) * 64 + b];
                u64 t0 = add2(rb[0 * 64],  rb[1 * 64]);
                u64 t1 = add2(rb[2 * 64],  rb[3 * 64]);
                u64 t2 = add2(rb[4 * 64],  rb[5 * 64]);
                u64 t3 = add2(rb[6 * 64],  rb[7 * 64]);
                u64 t4 = add2(rb[8 * 64],  rb[9 * 64]);
                u64 t5 = add2(rb[10 * 64], rb[11 * 64]);
                u64 t6 = add2(rb[12 * 64], rb[13 * 64]);
                u64 t7 = add2(rb[14 * 64], rb[15 * 64]);
                u64 u0 = add2(add2(t0, t1), add2(t2, t3));
                u64 u1 = add2(add2(t4, t5), add2(t6, t7));
                float2 r = unpack2(add2(u0, u1));
                gt[g] = (comp ? r.y : r.x) + xgv[g];
            }
            float ig = sigf(gt[0]), fg = sigf(gt[1]);
            float gg = tanh_f(gt[2]), og = sigf(gt[3]);
            c_reg = fg * c_reg + ig * gg;
            h_val = og * tanh_f(c_reg);
            __stcg(&g_h[s & 3][j * 64 + b], h_val);
        }
        __syncthreads();   // all h stores of this CTA issued before flag bump
        if (tid == 0) {
            asm volatile("red.release.gpu.global.add.u32 [%0], %1;"
                         :: "l"(&g_wf[cta]), "r"(1u) : "memory");
        }
    }

    if (tid < 256) {
        out[b * HH + j] = h_val;
        if (write_c) out[BB * HH + b * HH + j] = c_reg;
    }
}

// ---------------------------------------------------------------------------
// kernel_launch
// ---------------------------------------------------------------------------
extern "C" void kernel_launch(void* const* d_in, const int* in_sizes, int n_in,
                              void* d_out, int out_size)
{
    const void*  seq = d_in[0];
    const float* emb = (const float*)d_in[1];
    const float* Wih = (const float*)d_in[2];
    const float* Whh = (const float*)d_in[3];
    const float* bih = (const float*)d_in[4];
    const float* bhh = (const float*)d_in[5];
    float* out = (float*)d_out;

    (void)in_sizes; (void)n_in;
    int write_c = (out_size >= 2 * BB * HH) ? 1 : 0;

    // 96 KB dynamic SMEM: W pairs 32K + scratch 64K
    static const int kSmem = (8192 + 16384) * (int)sizeof(float);
    cudaFuncSetAttribute(lstm_kernel, cudaFuncAttributeMaxDynamicSharedMemorySize, kSmem);

    xgates_gemm<<<dim3(GG / 64, SS / 2), 256>>>(seq, emb, Wih, bih, bhh);
    lstm_kernel<<<HH / 4, 512, kSmem>>>(Whh, out, write_c);
}